// round 9
// baseline (speedup 1.0000x reference)
#include <cuda_runtime.h>
#include <cuda_fp16.h>
#include <math.h>

#define Bsz 128
#define Nn  512
#define Dd  64
#define KTOP 20
#define FULLMASK 0xFFFFFFFFu
#define NEG_SLOPE 0.2f
#define BN_EPS 1e-5f
#define NCTA 296

typedef unsigned long long ull;

// ---------------- scratch (device globals; no allocations) ----------------
__device__ __align__(16) __half2 g_z_h[Bsz*Nn*32];    // z as half2 (8.4MB)
__device__ __align__(16) __half2 g_rst_h[Bsz*Nn*32];  // rst as half2 (8.4MB)
__device__ __align__(16) float g_cos[Nn*Nn];          // 1 MB
__device__ float g_zsrc[Bsz*Nn];
__device__ float g_zdst[Bsz*Nn];
__device__ int   g_srcJ[KTOP*Nn];                     // j-major
__device__ float g_esrc[Nn];
__device__ float g_edst[Nn];
__device__ __align__(16) float g_sum[Dd];
__device__ __align__(16) float g_sumsq[Dd];
__device__ unsigned g_bcnt;                           // barrier count (self-reset)
__device__ unsigned g_bgen;                           // barrier generation (monotonic)

// ---------------- f32x2 packed helpers -------------------------------------
__device__ __forceinline__ ull pack2(float x, float y) {
    ull r; asm("mov.b64 %0, {%1, %2};" : "=l"(r) : "f"(x), "f"(y)); return r;
}
__device__ __forceinline__ void fma2(ull& d, ull a, ull b) {
    asm("fma.rn.f32x2 %0, %1, %2, %0;" : "+l"(d) : "l"(a), "l"(b));
}
__device__ __forceinline__ float2 unpack2(ull v) {
    float2 r; asm("mov.b64 {%0, %1}, %2;" : "=f"(r.x), "=f"(r.y) : "l"(v)); return r;
}

// ---------------- device-wide barrier (persistent grid, all-resident) ------
__device__ __forceinline__ void grid_sync_all() {
    __syncthreads();
    if (threadIdx.x == 0) {
        __threadfence();
        unsigned my  = atomicAdd(&g_bgen, 0u);        // read gen BEFORE arriving
        unsigned arr = atomicAdd(&g_bcnt, 1u);
        if (arr == NCTA - 1) {
            atomicExch(&g_bcnt, 0u);                  // reset for next barrier
            __threadfence();
            atomicAdd(&g_bgen, 1u);                   // release
        } else {
            while (atomicAdd(&g_bgen, 0u) == my) __nanosleep(64);
        }
        __threadfence();
    }
    __syncthreads();
}

// ---------------- phase A item: cos tile (item<64) or z-GEMM tile ---------
// 256-thread item; t = local tid (0..255); smh = 8896-float region.
__device__ __forceinline__ void phaseA_item(
    int item, int t, float* smh,
    const float* __restrict__ emb,  const float* __restrict__ data,
    const float* __restrict__ fc_w, const float* __restrict__ fc_b,
    const float* __restrict__ attn_w) {
    if (item < 64) {
        // -------- cosine tile --------
        float* At = smh;            // 64*68
        float* Bt = smh + 4352;     // 64*68
        float* rni = smh + 8704;    // 64
        float* rnj = rni + 64;      // 64
        int bb = item;
        int i0 = (bb >> 3) * 64, j0 = (bb & 7) * 64;
        for (int idx = t; idx < 4096; idx += 256) {
            int r = idx >> 6, k = idx & 63;
            At[k*68 + r] = emb[(i0 + r)*64 + k];
            Bt[k*68 + r] = emb[(j0 + r)*64 + k];
        }
        __syncthreads();
        if (t < 128) {
            int r = t & 63;
            const float* T = (t >= 64) ? Bt : At;
            float s = 0.f;
#pragma unroll
            for (int k = 0; k < 64; ++k) { float v = T[k*68 + r]; s = fmaf(v, v, s); }
            float inv = 1.0f / sqrtf(s);
            if (t >= 64) rnj[r] = inv; else rni[r] = inv;
        } else if (bb < 8) {
            int r = t & 63;
            int which = (t >= 192);
            const float* awp = attn_w + (which ? 3*Dd : Dd);
            float acc = 0.f;
#pragma unroll
            for (int k = 0; k < 64; ++k)
                acc = fmaf(Bt[k*68 + r], awp[k], acc);
            if (which) g_edst[j0 + r] = acc;
            else       g_esrc[j0 + r] = acc;
        }
        __syncthreads();
        int tx = t & 15, ty = t >> 4;
        int r0 = ty * 4, c0 = tx * 4;
        float acc[4][4] = {};
#pragma unroll 8
        for (int k = 0; k < 64; ++k) {
            float4 a4 = *(const float4*)&At[k*68 + r0];
            float4 b4 = *(const float4*)&Bt[k*68 + c0];
            float av[4] = {a4.x, a4.y, a4.z, a4.w};
            float bv[4] = {b4.x, b4.y, b4.z, b4.w};
#pragma unroll
            for (int r = 0; r < 4; ++r)
#pragma unroll
                for (int c = 0; c < 4; ++c)
                    acc[r][c] = fmaf(av[r], bv[c], acc[r][c]);
        }
        float rj[4];
#pragma unroll
        for (int c = 0; c < 4; ++c) rj[c] = rnj[c0 + c];
#pragma unroll
        for (int r = 0; r < 4; ++r) {
            float ri = rni[r0 + r];
            float4 o;
            o.x = acc[r][0] * ri * rj[0];
            o.y = acc[r][1] * ri * rj[1];
            o.z = acc[r][2] * ri * rj[2];
            o.w = acc[r][3] * ri * rj[3];
            *(float4*)&g_cos[(i0 + r0 + r)*Nn + j0 + c0] = o;
        }
        __syncthreads();        // match gemm branch sync count
    } else {
        // -------- z-GEMM tile: 64 rows --------
        float* At  = smh;                      // 64*68 (reused as z_s)
        ull*   wP  = (ull*)(smh + 4352);       // 64*34
        float* aws = smh + 8704;               // 64
        float* awd = aws + 64;                 // 64
        float* bias= awd + 64;                 // 64
        int zb = item - 64;                    // 0..1023
        int m0 = zb * 64;

        if (zb == 0 && t >= 128 && t < 256) {
            int tt = t - 128;
            if (tt < 64) g_sum[tt] = 0.f; else g_sumsq[tt - 64] = 0.f;
        }
        for (int idx = t; idx < 1024; idx += 256) {
            int r = idx >> 4, kq = idx & 15;
            float4 v = *(const float4*)&data[(m0 + r)*64 + 4*kq];
            At[(4*kq+0)*68 + r] = v.x;
            At[(4*kq+1)*68 + r] = v.y;
            At[(4*kq+2)*68 + r] = v.z;
            At[(4*kq+3)*68 + r] = v.w;
        }
        for (int idx = t; idx < 512; idx += 256) {
            int cp = idx >> 4, kq = idx & 15;
            float4 lo = *(const float4*)&fc_w[(2*cp)*64 + 4*kq];
            float4 hi = *(const float4*)&fc_w[(2*cp+1)*64 + 4*kq];
            wP[(4*kq+0)*34 + cp] = pack2(lo.x, hi.x);
            wP[(4*kq+1)*34 + cp] = pack2(lo.y, hi.y);
            wP[(4*kq+2)*34 + cp] = pack2(lo.z, hi.z);
            wP[(4*kq+3)*34 + cp] = pack2(lo.w, hi.w);
        }
        if (t < 64) {
            bias[t] = fc_b[t];
            aws[t]  = attn_w[t];
            awd[t]  = attn_w[128 + t];
        }
        __syncthreads();

        int tx = t & 15, ty = t >> 4;
        int r0 = ty * 4;
        ull acc[4][2] = {};
#pragma unroll 8
        for (int k = 0; k < 64; ++k) {
            float4 a4 = *(const float4*)&At[k*68 + r0];
            ulonglong2 w2 = *(const ulonglong2*)&wP[k*34 + 2*tx];
            ull pa0 = pack2(a4.x, a4.x), pa1 = pack2(a4.y, a4.y);
            ull pa2 = pack2(a4.z, a4.z), pa3 = pack2(a4.w, a4.w);
            fma2(acc[0][0], pa0, w2.x); fma2(acc[0][1], pa0, w2.y);
            fma2(acc[1][0], pa1, w2.x); fma2(acc[1][1], pa1, w2.y);
            fma2(acc[2][0], pa2, w2.x); fma2(acc[2][1], pa2, w2.y);
            fma2(acc[3][0], pa3, w2.x); fma2(acc[3][1], pa3, w2.y);
        }
        __syncthreads();
        float* z_s = At;
        float b0 = bias[4*tx], b1 = bias[4*tx+1], b2 = bias[4*tx+2], b3 = bias[4*tx+3];
#pragma unroll
        for (int r = 0; r < 4; ++r) {
            float2 v0 = unpack2(acc[r][0]);
            float2 v1 = unpack2(acc[r][1]);
            float z0 = v0.x + b0, z1 = v0.y + b1;
            float z2 = v1.x + b2, z3 = v1.y + b3;
            int row = m0 + r0 + r;
            g_z_h[row*32 + 2*tx]     = __floats2half2_rn(z0, z1);
            g_z_h[row*32 + 2*tx + 1] = __floats2half2_rn(z2, z3);
            float* zp = &z_s[(r0 + r)*68 + 4*tx];
            zp[0] = z0; zp[1] = z1; zp[2] = z2; zp[3] = z3;
        }
        __syncthreads();
        if (t < 128) {
            int n = t >> 1, half = t & 1, k0 = half * 32;
            float s1 = 0.f, s2 = 0.f;
#pragma unroll
            for (int k = 0; k < 32; ++k) {
                float zv = z_s[n*68 + k0 + k];
                s1 = fmaf(zv, aws[k0 + k], s1);
                s2 = fmaf(zv, awd[k0 + k], s2);
            }
            s1 += __shfl_xor_sync(FULLMASK, s1, 1);
            s2 += __shfl_xor_sync(FULLMASK, s2, 1);
            if (half == 0) {
                g_zsrc[m0 + n] = s1;
                g_zdst[m0 + n] = s2;
            }
        }
    }
}

// ===========================================================================
// MEGA: all phases in one persistent launch (296 CTAs x 512 thr, 2/SM)
// ===========================================================================
__global__ void __launch_bounds__(512, 2)
mega(const float* __restrict__ emb,   const float* __restrict__ data,
     const float* __restrict__ fc_w,  const float* __restrict__ fc_b,
     const float* __restrict__ attn_w,const float* __restrict__ attn_b_p,
     const float* __restrict__ gamma, const float* __restrict__ beta,
     const float* __restrict__ out_w, const float* __restrict__ out_b_p,
     float* __restrict__ out) {
    extern __shared__ float smf[];
    char* smc = (char*)smf;
    int tid = threadIdx.x;
    int bid = blockIdx.x;

    // ---------------- Phase A: cosine + z-GEMM (1088 items, 2/CTA-pass) ----
    {
        int h = tid >> 8, t = tid & 255;
        float* smh = smf + h * 8896;
#pragma unroll
        for (int it = 0; it < 2; ++it) {
            int base = it * 592 + 2 * bid;
            if (base >= 1088) break;               // CTA-uniform
            phaseA_item(base + h, t, smh, emb, data, fc_w, fc_b, attn_w);
            __syncthreads();
        }
    }
    grid_sync_all();

    // ---------------- Phase B: top-20 per row (warp per row) ---------------
    {
        int gw   = bid * 16 + (tid >> 5);
        int lane = tid & 31;
        if (gw < Nn) {
            const float* row = g_cos + gw * Nn;
            float v[16];
#pragma unroll
            for (int tt = 0; tt < 16; ++tt) v[tt] = row[tt*32 + lane];
            float bv = v[0]; int bt = 0;
#pragma unroll
            for (int tt = 1; tt < 16; ++tt) if (v[tt] > bv) { bv = v[tt]; bt = tt; }
            for (int itk = 0; itk < KTOP; ++itk) {
                float rv = bv; int ri = bt*32 + lane;
#pragma unroll
                for (int off = 16; off; off >>= 1) {
                    float ov = __shfl_down_sync(FULLMASK, rv, off);
                    int   oi = __shfl_down_sync(FULLMASK, ri, off);
                    if (ov > rv || (ov == rv && oi < ri)) { rv = ov; ri = oi; }
                }
                ri = __shfl_sync(FULLMASK, ri, 0);
                if (lane == 0) {
                    int F = gw * KTOP + itk;
                    g_srcJ[(F >> 9) * Nn + (F & 511)] = ri;
                }
                if ((ri & 31) == lane) {
                    int kt = ri >> 5;
#pragma unroll
                    for (int tt = 0; tt < 16; ++tt) if (tt == kt) v[tt] = -INFINITY;
                    bv = v[0]; bt = 0;
#pragma unroll
                    for (int tt = 1; tt < 16; ++tt) if (v[tt] > bv) { bv = v[tt]; bt = tt; }
                }
            }
        }
    }
    grid_sync_all();

    // ---------------- Phase C: attention (512 units of 128 dst) ------------
    {
        float2*  als  = (float2*)smc;                      // 128*20
        __half2* z_h  = (__half2*)(smc + 20480);           // 512*34
        float*   ssrc = (float*)(smc + 90112);             // 512
        float*   sdst = (float*)(smc + 92160);             // 512
        float*   wbufS = (float*)smc;                      // overlay
        float*   wbufQ = (float*)(smc + 4352);
        int w = tid >> 5, lane = tid & 31;

#pragma unroll
        for (int it = 0; it < 2; ++it) {
            int unit = it * NCTA + bid;
            if (unit >= Bsz * 4) break;                    // CTA-uniform
            int b = unit >> 2;
            int dbase = (unit & 3) * 128;

            {
                const uint4* zg = (const uint4*)(g_z_h + (size_t)b * Nn * 32);
                unsigned* zu = (unsigned*)z_h;
#pragma unroll
                for (int it2 = 0; it2 < 8; ++it2) {
                    int i = tid + it2 * 512;
                    uint4 v = zg[i];
                    int n = i >> 3, c0 = (i & 7) * 4;
                    uint2* p = (uint2*)(zu + n*34 + c0);
                    p[0] = make_uint2(v.x, v.y);
                    p[1] = make_uint2(v.z, v.w);
                }
            }
            ssrc[tid] = g_zsrc[b*Nn + tid] + g_esrc[tid];
            sdst[tid] = g_zdst[b*Nn + tid] + g_edst[tid];
            __syncthreads();

            {
                const float ab = *attn_b_p;
                int dl = tid >> 2, q = tid & 3;
                int d = dbase + dl;
                float sd = sdst[d];
                float sc[5]; int si[5];
#pragma unroll
                for (int j5 = 0; j5 < 5; ++j5) {
                    int j = q * 5 + j5;
                    int s = g_srcJ[j * Nn + d];
                    si[j5] = s;
                    float x = ssrc[s] + sd + ab;
                    sc[j5] = (x > 0.f) ? x : NEG_SLOPE * x;
                }
                float m = sc[0];
#pragma unroll
                for (int j5 = 1; j5 < 5; ++j5) m = fmaxf(m, sc[j5]);
                m = fmaxf(m, __shfl_xor_sync(FULLMASK, m, 1));
                m = fmaxf(m, __shfl_xor_sync(FULLMASK, m, 2));
                float p[5], ps = 0.f;
#pragma unroll
                for (int j5 = 0; j5 < 5; ++j5) { p[j5] = expf(sc[j5] - m); ps += p[j5]; }
                ps += __shfl_xor_sync(FULLMASK, ps, 1);
                ps += __shfl_xor_sync(FULLMASK, ps, 2);
                float inv = 1.0f / ps;
#pragma unroll
                for (int j5 = 0; j5 < 5; ++j5) {
                    int j = q * 5 + j5;
                    als[dl*KTOP + j] = make_float2(p[j5] * inv, __int_as_float(si[j5]));
                }
            }
            __syncthreads();

            float acc_s0 = 0.f, acc_q0 = 0.f, acc_s1 = 0.f, acc_q1 = 0.f;
            for (int r = 0; r < 8; r += 2) {
                int dlA = w * 8 + r, dlB = dlA + 1;
                float hA0 = 0.f, hA1 = 0.f, hB0 = 0.f, hB1 = 0.f;
#pragma unroll
                for (int jj = 0; jj < 10; ++jj) {
                    float4 qA = *(const float4*)&als[dlA*KTOP + jj*2];
                    float4 qB = *(const float4*)&als[dlB*KTOP + jj*2];
                    int a0 = __float_as_int(qA.y), a1 = __float_as_int(qA.w);
                    int b0 = __float_as_int(qB.y), b1 = __float_as_int(qB.w);
                    float2 fa0 = __half22float2(z_h[a0*34 + lane]);
                    float2 fa1 = __half22float2(z_h[a1*34 + lane]);
                    float2 fb0 = __half22float2(z_h[b0*34 + lane]);
                    float2 fb1 = __half22float2(z_h[b1*34 + lane]);
                    hA0 = fmaf(qA.x, fa0.x, hA0); hA1 = fmaf(qA.x, fa0.y, hA1);
                    hA0 = fmaf(qA.z, fa1.x, hA0); hA1 = fmaf(qA.z, fa1.y, hA1);
                    hB0 = fmaf(qB.x, fb0.x, hB0); hB1 = fmaf(qB.x, fb0.y, hB1);
                    hB0 = fmaf(qB.z, fb1.x, hB0); hB1 = fmaf(qB.z, fb1.y, hB1);
                }
                int dA = dbase + dlA, dB = dbase + dlB;
                float2 eA = *(const float2*)&emb[dA*64 + 2*lane];
                float2 eB = *(const float2*)&emb[dB*64 + 2*lane];
                float rA0 = hA0 * eA.x, rA1 = hA1 * eA.y;
                float rB0 = hB0 * eB.x, rB1 = hB1 * eB.y;
                g_rst_h[((size_t)b*Nn + dA)*32 + lane] = __floats2half2_rn(rA0, rA1);
                g_rst_h[((size_t)b*Nn + dB)*32 + lane] = __floats2half2_rn(rB0, rB1);
                acc_s0 += rA0 + rB0; acc_q0 = fmaf(rA0, rA0, fmaf(rB0, rB0, acc_q0));
                acc_s1 += rA1 + rB1; acc_q1 = fmaf(rA1, rA1, fmaf(rB1, rB1, acc_q1));
            }
            __syncthreads();
            wbufS[w*66 + 2*lane]     = acc_s0;
            wbufS[w*66 + 2*lane + 1] = acc_s1;
            wbufQ[w*66 + 2*lane]     = acc_q0;
            wbufQ[w*66 + 2*lane + 1] = acc_q1;
            __syncthreads();
            if (tid < 64) {
                float s = 0.f, q = 0.f;
#pragma unroll
                for (int ww = 0; ww < 16; ++ww) {
                    s += wbufS[ww*66 + tid];
                    q += wbufQ[ww*66 + tid];
                }
                atomicAdd(&g_sum[tid],   s);
                atomicAdd(&g_sumsq[tid], q);
            }
            __syncthreads();
        }
    }
    grid_sync_all();

    // ---------------- Phase D: BN finalize + BN + relu + output ------------
    {
        float* sc_s = smf;          // 64
        float* sh_s = smf + 64;     // 64
        float* wv   = smf + 128;    // 64
        if (tid < 64) {
            int t = tid;
            const float inv_n = 1.0f / (float)(Bsz * Nn);
            float mu  = g_sum[t] * inv_n;
            float var = g_sumsq[t] * inv_n - mu * mu;
            float s   = gamma[t] / sqrtf(var + BN_EPS);
            sc_s[t] = s;
            sh_s[t] = beta[t] - mu * s;
            wv[t]   = out_w[t];
        }
        __syncthreads();
        int gt   = bid * 512 + tid;
        int row  = gt >> 1, half = gt & 1;
        if (row < Bsz * Nn) {
            const uint4* rp = (const uint4*)(g_rst_h + (size_t)row * 32 + half * 16);
            uint4 u0 = rp[0], u1 = rp[1], u2 = rp[2], u3 = rp[3];
            unsigned uu[16] = {u0.x,u0.y,u0.z,u0.w, u1.x,u1.y,u1.z,u1.w,
                               u2.x,u2.y,u2.z,u2.w, u3.x,u3.y,u3.z,u3.w};
            float s = 0.f;
            int cb = half * 32;
#pragma unroll
            for (int p = 0; p < 16; ++p) {
                float2 f0 = __half22float2(*(__half2*)&uu[p]);
                int ch = cb + 2*p;
                s += fmaxf(fmaf(f0.x, sc_s[ch],   sh_s[ch]),   0.f) * wv[ch];
                s += fmaxf(fmaf(f0.y, sc_s[ch+1], sh_s[ch+1]), 0.f) * wv[ch+1];
            }
            s += __shfl_xor_sync(FULLMASK, s, 1);
            if (half == 0) out[row] = s + *out_b_p;
        }
    }
}

// ---------------- launch ----------------------------------------------------
extern "C" void kernel_launch(void* const* d_in, const int* in_sizes, int n_in,
                              void* d_out, int out_size) {
    const float* data     = (const float*)d_in[0];
    const float* emb      = (const float*)d_in[1];
    const float* fc_w     = (const float*)d_in[2];
    const float* fc_b     = (const float*)d_in[3];
    const float* attn_w   = (const float*)d_in[4];
    const float* attn_b   = (const float*)d_in[5];
    const float* bn_gamma = (const float*)d_in[6];
    const float* bn_beta  = (const float*)d_in[7];
    const float* out_w    = (const float*)d_in[8];
    const float* out_b    = (const float*)d_in[9];
    float* out = (float*)d_out;

    const int SMEM = 94208;   // bytes: max(phase A 71168, phase C 94208)
    cudaFuncSetAttribute(mega, cudaFuncAttributeMaxDynamicSharedMemorySize, SMEM);

    mega<<<NCTA, 512, SMEM>>>(emb, data, fc_w, fc_b, attn_w, attn_b,
                              bn_gamma, bn_beta, out_w, out_b, out);
}